// round 17
// baseline (speedup 1.0000x reference)
#include <cuda_runtime.h>
#include <float.h>

#define NDET      5000
#define TOPK      1000
#define NCLS      80
#define DETSTRIDE 84
#define CH        256
#define CROP      14

// Scratch (no allocations allowed in kernel_launch)
__device__ float  g_scores[NDET];
__device__ float4 g_allbox[NDET];        // per-row box (precomputed)
__device__ int    g_alllev[NDET];        // per-row FPN level (precomputed)
__device__ int    g_sel[TOPK];           // rank -> original detection row
__device__ float4 g_boxes[TOPK];         // boxes after stable level sort
__device__ int    g_level[TOPK];
__device__ int    g_done;                // k_rank completion counter

// ---------------------------------------------------------------------------
// K1: per-row max over 80 class scores (warp per row) + per-row box/level
// precompute (lane 0) + g_done reset.
// ---------------------------------------------------------------------------
__global__ void __launch_bounds__(256) k_scores(const float* __restrict__ det) {
    int gtid = blockIdx.x * blockDim.x + threadIdx.x;
    if (gtid == 0) g_done = 0;
    int warp = gtid >> 5;
    int lane = threadIdx.x & 31;
    if (warp >= NDET) return;
    const float* prow = det + (size_t)warp * DETSTRIDE;
    float m = -FLT_MAX;
    for (int i = 4 + lane; i < 4 + NCLS; i += 32) m = fmaxf(m, prow[i]);
#pragma unroll
    for (int off = 16; off > 0; off >>= 1)
        m = fmaxf(m, __shfl_xor_sync(0xffffffffu, m, off));
    if (lane == 0) {
        g_scores[warp] = m;
        float4 bx = *(const float4*)prow;        // 336B row stride -> 16B aligned
        float size = sqrtf((bx.z - bx.x) * (bx.w - bx.y));
        float lv = floorf(1.0f + log2f(size / 224.0f + 1e-7f));
        lv = fminf(fmaxf(lv, 0.0f), 4.0f);
        g_allbox[warp] = bx;
        g_alllev[warp] = (int)lv;
    }
}

// ---------------------------------------------------------------------------
// K2: exact jax.lax.top_k rank counting (8 rows/block, 625 blocks) with the
// stable level-sort FUSED via last-block-done: the block that observes all
// 625 completions runs the single-block counting sort with its 1024 threads.
// ---------------------------------------------------------------------------
#define RPB 8
__global__ void __launch_bounds__(1024) k_rank_sort() {
    __shared__ int blockcnt[RPB];
    __shared__ int s_last;
    int tid = threadIdx.x;
    int base = blockIdx.x * RPB;
    if (tid < RPB) blockcnt[tid] = 0;

    float sr[RPB];
#pragma unroll
    for (int k = 0; k < RPB; k++) sr[k] = __ldg(&g_scores[base + k]);

    int cnt[RPB];
#pragma unroll
    for (int k = 0; k < RPB; k++) cnt[k] = 0;

    __syncthreads();
#pragma unroll
    for (int it = 0; it < (NDET + 1023) / 1024; it++) {
        int j = it * 1024 + tid;
        if (j < NDET) {
            float sj = __ldg(&g_scores[j]);
#pragma unroll
            for (int k = 0; k < RPB; k++)
                cnt[k] += (sj > sr[k] || (sj == sr[k] && j < base + k)) ? 1 : 0;
        }
    }
#pragma unroll
    for (int k = 0; k < RPB; k++) {
#pragma unroll
        for (int off = 16; off > 0; off >>= 1)
            cnt[k] += __shfl_down_sync(0xffffffffu, cnt[k], off);
    }
    if ((tid & 31) == 0) {
#pragma unroll
        for (int k = 0; k < RPB; k++)
            if (cnt[k] > 0) atomicAdd(&blockcnt[k], cnt[k]);
    }
    __syncthreads();
    if (tid < RPB) {
        int rank = blockcnt[tid];
        if (rank < TOPK) g_sel[rank] = base + tid;
    }

    // ---- last-block-done handoff ----
    __syncthreads();
    if (tid == 0) {
        __threadfence();
        s_last = (atomicAdd(&g_done, 1) == (NDET / RPB) - 1) ? 1 : 0;
    }
    __syncthreads();
    if (!s_last) return;
    __threadfence();

    // ---- fused stable counting sort by level (1024 threads) ----
    int r = tid;
    float4 bx = make_float4(0.f, 0.f, 0.f, 0.f);
    int lev = 0;
    unsigned long long onehot = 0ULL;
    if (r < TOPK) {
        int row = g_sel[r];
        bx = g_allbox[row];
        lev = g_alllev[row];
        onehot = 1ULL << (10 * lev);
    }
    unsigned long long v = onehot;
    int lane = r & 31;
#pragma unroll
    for (int off = 1; off < 32; off <<= 1) {
        unsigned long long n = __shfl_up_sync(0xffffffffu, v, off);
        if (lane >= off) v += n;
    }
    __shared__ unsigned long long warpsum[32];
    int wid = r >> 5;
    if (lane == 31) warpsum[wid] = v;
    __syncthreads();
    if (r < 32) {
        unsigned long long w = warpsum[r];
#pragma unroll
        for (int off = 1; off < 32; off <<= 1) {
            unsigned long long n = __shfl_up_sync(0xffffffffu, w, off);
            if (r >= off) w += n;
        }
        warpsum[r] = w;
    }
    __syncthreads();
    unsigned long long incl = v + (wid > 0 ? warpsum[wid - 1] : 0ULL);
    unsigned long long total = warpsum[31];
    unsigned long long excl = incl - onehot;
    if (r < TOPK) {
        int before = 0;
#pragma unroll
        for (int l = 0; l < 4; l++)
            if (l < lev) before += (int)((total >> (10 * l)) & 1023ULL);
        int pos = before + (int)((excl >> (10 * lev)) & 1023ULL);
        g_boxes[pos] = bx;
        g_level[pos] = lev;
    }
}

// ---------------------------------------------------------------------------
// K4: crop_and_resize. EXACT R15 config (best measured: 43.1us).
// 128-thread block = (box, y-half), grid 2000, launch_bounds(128,4).
// Valid x-columns compacted + padded to multiple of 6; 6 points/iter =
// 24 independent LDG.128 per thread (natural regs, no squeeze).
// ---------------------------------------------------------------------------
#define UW 6
__global__ void __launch_bounds__(128, 4) k_main(
    const float* __restrict__ p0, const float* __restrict__ p1,
    const float* __restrict__ p2, const float* __restrict__ p3,
    const float* __restrict__ p4, float* __restrict__ out)
{
    __shared__ float s_lx[CROP], s_ly[CROP];
    __shared__ int   s_x0[CROP], s_x1[CROP];   // float4 offsets within a row
    __shared__ int   s_r0[CROP], s_r1[CROP];   // float4 offsets of rows
    __shared__ int   s_vx[CROP], s_vy[CROP];
    __shared__ int   s_xlist[CROP + UW - 1], s_xinv[CROP];
    __shared__ int   s_nx, s_ninv;

    int tid  = threadIdx.x;
    int b    = blockIdx.x >> 1;
    int half = blockIdx.x & 1;
    float4 box = g_boxes[b];
    int lev = g_level[b];

    const float* feat;
    int S;
    switch (lev) {
        case 0:  feat = p0; S = 256; break;
        case 1:  feat = p1; S = 128; break;
        case 2:  feat = p2; S = 64;  break;
        case 3:  feat = p3; S = 32;  break;
        default: feat = p4; S = 16;  break;
    }
    float hf = (float)(S - 1);

    if (tid < 2 * CROP) {
        int i = tid;
        bool isy = i >= CROP;
        int k = isy ? i - CROP : i;
        float a1 = isy ? box.y : box.x;
        float a2 = isy ? box.w : box.z;
        // reference normalizes then rescales by the same (S-1) factor
        float n1 = a1 / hf, n2 = a2 / hf;
        float t = (float)k / 13.0f;
        float s = (n1 + (n2 - n1) * t) * hf;
        int valid = (s >= 0.0f && s <= hf) ? 1 : 0;
        float f0 = floorf(s);
        float l = s - f0;
        int i0 = (int)fminf(fmaxf(f0, 0.0f), hf);
        int i1 = (int)fminf(fmaxf(f0 + 1.0f, 0.0f), hf);
        if (isy) {
            s_ly[k] = l; s_vy[k] = valid;
            s_r0[k] = i0 * S * (CH / 4);
            s_r1[k] = i1 * S * (CH / 4);
        } else {
            s_lx[k] = l; s_vx[k] = valid;
            s_x0[k] = i0 * (CH / 4);
            s_x1[k] = i1 * (CH / 4);
        }
    }
    __syncthreads();
    if (tid == 0) {
        int n = 0, m = 0;
#pragma unroll
        for (int i = 0; i < CROP; i++) {
            if (s_vx[i]) s_xlist[n++] = i;
            else         s_xinv[m++]  = i;
        }
        s_nx = n; s_ninv = m;
        if (n > 0) {                      // pad to multiple of UW
            int last = s_xlist[n - 1];
            while (n % UW) s_xlist[n++] = last;
        }
    }
    __syncthreads();

    int cg = tid & 63;           // channel group (float4)
    int rg = tid >> 6;           // row group (0..1)
    const float4* fp = (const float4*)feat;
    const float4 zero4 = make_float4(0.f, 0.f, 0.f, 0.f);
    int nv = s_nx, ni = s_ninv;
    int nvp = ((nv + UW - 1) / UW) * UW;
    int ybase = half * 7;        // rows [ybase, ybase+7)

    for (int yi = ybase + rg; yi < ybase + 7; yi += 2) {
        float4* orow = (float4*)(out + (((size_t)b * CROP + yi) * CROP) * CH) + cg;

        if (!s_vy[yi]) {
#pragma unroll
            for (int xi = 0; xi < CROP; xi++)
                __stcs(orow + (size_t)xi * 64, zero4);
            continue;
        }

        // zero-fill invalid columns (no loads)
        for (int k = 0; k < ni; k++)
            __stcs(orow + (size_t)s_xinv[k] * 64, zero4);

        int r0 = s_r0[yi] + cg;
        int r1 = s_r1[yi] + cg;
        float ly = s_ly[yi];

        for (int j = 0; j < nvp; j += UW) {
            int   xq[UW];
            int   q0[UW], q1[UW];
            float lx[UW];
#pragma unroll
            for (int q = 0; q < UW; q++) {
                xq[q] = s_xlist[j + q];
                q0[q] = s_x0[xq[q]];
                q1[q] = s_x1[xq[q]];
                lx[q] = s_lx[xq[q]];
            }
            float4 F00[UW], F01[UW], F10[UW], F11[UW];
#pragma unroll
            for (int q = 0; q < UW; q++) {
                F00[q] = __ldg(fp + r0 + q0[q]);
                F01[q] = __ldg(fp + r0 + q1[q]);
                F10[q] = __ldg(fp + r1 + q0[q]);
                F11[q] = __ldg(fp + r1 + q1[q]);
            }
#pragma unroll
            for (int q = 0; q < UW; q++) {
                float4 v;
                float t, bo;
                t = F00[q].x + (F01[q].x - F00[q].x) * lx[q];
                bo = F10[q].x + (F11[q].x - F10[q].x) * lx[q];
                v.x = t + (bo - t) * ly;
                t = F00[q].y + (F01[q].y - F00[q].y) * lx[q];
                bo = F10[q].y + (F11[q].y - F10[q].y) * lx[q];
                v.y = t + (bo - t) * ly;
                t = F00[q].z + (F01[q].z - F00[q].z) * lx[q];
                bo = F10[q].z + (F11[q].z - F10[q].z) * lx[q];
                v.z = t + (bo - t) * ly;
                t = F00[q].w + (F01[q].w - F00[q].w) * lx[q];
                bo = F10[q].w + (F11[q].w - F10[q].w) * lx[q];
                v.w = t + (bo - t) * ly;
                __stcs(orow + (size_t)xq[q] * 64, v);
            }
        }
    }
}

// ---------------------------------------------------------------------------
extern "C" void kernel_launch(void* const* d_in, const int* in_sizes, int n_in,
                              void* d_out, int out_size) {
    const float* det = (const float*)d_in[0];
    const float* p0  = (const float*)d_in[1];
    const float* p1  = (const float*)d_in[2];
    const float* p2  = (const float*)d_in[3];
    const float* p3  = (const float*)d_in[4];
    const float* p4  = (const float*)d_in[5];
    float* out = (float*)d_out;

    k_scores<<<(NDET * 32 + 255) / 256, 256>>>(det);
    k_rank_sort<<<NDET / RPB, 1024>>>();
    k_main<<<TOPK * 2, 128>>>(p0, p1, p2, p3, p4, out);
}